// round 7
// baseline (speedup 1.0000x reference)
#include <cuda_runtime.h>
#include <cuda_bf16.h>
#include <cstdint>

#define STX 132      // xs-kernel smem stride (proven)
#define ATS 144      // main A stride in bf16 (288B: conflict-free half-warp LDS.64)

// Scratch for x_s = x @ Wx^T + bx
__device__ float g_xs[65536 * 128];

__device__ __forceinline__ uint32_t f2tf32(float f) {
    uint32_t r; asm volatile("cvt.rna.tf32.f32 %0, %1;" : "=r"(r) : "f"(f)); return r;
}
__device__ __forceinline__ void mma_tf32_frag(float c[4], const uint32_t a[4], const uint32_t b[2]) {
    asm volatile(
        "mma.sync.aligned.m16n8k8.row.col.f32.tf32.tf32.f32 "
        "{%0,%1,%2,%3}, {%4,%5,%6,%7}, {%8,%9}, {%0,%1,%2,%3};"
        : "+f"(c[0]), "+f"(c[1]), "+f"(c[2]), "+f"(c[3])
        : "r"(a[0]), "r"(a[1]), "r"(a[2]), "r"(a[3]), "r"(b[0]), "r"(b[1]));
}
__device__ __forceinline__ void mma_bf16(float c[4], const uint32_t a[4], const uint32_t b[2]) {
    asm volatile(
        "mma.sync.aligned.m16n8k16.row.col.f32.bf16.bf16.f32 "
        "{%0,%1,%2,%3}, {%4,%5,%6,%7}, {%8,%9}, {%0,%1,%2,%3};"
        : "+f"(c[0]), "+f"(c[1]), "+f"(c[2]), "+f"(c[3])
        : "r"(a[0]), "r"(a[1]), "r"(a[2]), "r"(a[3]), "r"(b[0]), "r"(b[1]));
}
__device__ __forceinline__ uint32_t pack_bf16(float lo, float hi) {
    __nv_bfloat162 v = __floats2bfloat162_rn(lo, hi);
    return *reinterpret_cast<uint32_t*>(&v);
}

// ---------------------------------------------------------------------------
// Kernel 1: x_s = x @ Wx^T + bx. 4 tiles per CTA: Wx loaded once, amortized.
// ---------------------------------------------------------------------------
__global__ __launch_bounds__(256) void xs_kernel(
    const float* __restrict__ x, const float* __restrict__ Wx,
    const float* __restrict__ bx, int N)
{
    extern __shared__ float smem[];
    float* sW  = smem;
    float* sA  = sW + 128 * STX;
    float* sbx = sA + 128 * STX;
    const int tid = threadIdx.x;

    for (int i = tid; i < 128 * 128; i += 256) {
        int d = i >> 7, e = i & 127;
        ((uint32_t*)sW)[d * STX + e] = f2tf32(Wx[i]);
    }
    if (tid < 128) sbx[tid] = bx[tid];

    const int w = tid >> 5, lane = tid & 31;
    const int lg = lane >> 2, lc = lane & 3;
    const int wm = w >> 1, wn = w & 1;
    const uint32_t* uA = (const uint32_t*)sA;
    const uint32_t* uW = (const uint32_t*)sW;

    for (int s = 0; s < 4; s++) {
        const int tileBase = (blockIdx.x * 4 + s) * 128;
        if (tileBase >= N) break;   // uniform

        __syncthreads();   // sW ready (s=0) / prior tile fully consumed (s>0)
        for (int i = tid; i < 128 * 128; i += 256) {
            int r = i >> 7, e = i & 127;
            int node = tileBase + r;
            float v = (node < N) ? x[node * 128 + e] : 0.f;
            ((uint32_t*)sA)[r * STX + e] = f2tf32(v);
        }
        __syncthreads();

        float acc[2][8][4];
#pragma unroll
        for (int mi = 0; mi < 2; mi++)
#pragma unroll
            for (int ni = 0; ni < 8; ni++)
#pragma unroll
                for (int j = 0; j < 4; j++) acc[mi][ni][j] = 0.f;

#pragma unroll 4
        for (int ks = 0; ks < 16; ks++) {
            const int e0 = ks * 8;
            uint32_t afr[2][4];
#pragma unroll
            for (int mi = 0; mi < 2; mi++) {
                int r = wm * 32 + mi * 16 + lg;
                afr[mi][0] = uA[r * STX + e0 + lc];
                afr[mi][1] = uA[(r + 8) * STX + e0 + lc];
                afr[mi][2] = uA[r * STX + e0 + 4 + lc];
                afr[mi][3] = uA[(r + 8) * STX + e0 + 4 + lc];
            }
#pragma unroll
            for (int ni = 0; ni < 8; ni++) {
                int c0 = wn * 64 + ni * 8;
                uint32_t bfr[2];
                bfr[0] = uW[(c0 + lg) * STX + e0 + lc];
                bfr[1] = uW[(c0 + lg) * STX + e0 + 4 + lc];
                mma_tf32_frag(acc[0][ni], afr[0], bfr);
                mma_tf32_frag(acc[1][ni], afr[1], bfr);
            }
        }
#pragma unroll
        for (int mi = 0; mi < 2; mi++)
#pragma unroll
            for (int rh = 0; rh < 2; rh++) {
                int r = wm * 32 + mi * 16 + rh * 8 + lg;
                int node = tileBase + r;
                if (node < N) {
#pragma unroll
                    for (int ni = 0; ni < 8; ni++)
#pragma unroll
                        for (int cc = 0; cc < 2; cc++) {
                            int d = wn * 64 + ni * 8 + 2 * lc + cc;
                            g_xs[node * 128 + d] = acc[mi][ni][rh * 2 + cc] + sbx[d];
                        }
                }
            }
    }
}

// ---------------------------------------------------------------------------
// Main kernel: persistent, 256 threads, 2 CTAs/SM, double-buffered sA,
// software-pipelined tile load: LDG(t+1) issues after scores(t), its latency
// hides behind softmax+output(t); convert+STS after output. 2 barriers/tile.
// 8 warps = 2(wm:M32) x 4(wn:N32), K=128, bf16 m16n8k16, Wn B-frags in regs,
// A via LDS.64 with physical-k pair remap (round-5 proven layout).
// ---------------------------------------------------------------------------
__global__ __launch_bounds__(256, 2) void gnn_main_kernel(
    const float* __restrict__ x_nb, const float* __restrict__ weight,
    const float* __restrict__ Wn, const float* __restrict__ bn,
    const float* __restrict__ Ww, const float* __restrict__ bw,
    const float* __restrict__ Wl,
    float* __restrict__ out, int N, int numTiles)
{
    __shared__ __align__(16) __nv_bfloat16 sA[2][64 * ATS];  // 2 x 18432 B
    __shared__ float sxs[2][256];
    __shared__ float swt[2][64];
    __shared__ __align__(16) float spart[256];   // [row 0..63][wn 0..3]
    __shared__ float scb[128];
    __shared__ float sWw[128];
    __shared__ float sWl[128];

    const int tid  = threadIdx.x;
    const int w    = tid >> 5, lane = tid & 31;
    const int lg   = lane >> 2, lc = lane & 3;
    const int wm   = w >> 2;     // 0..1
    const int wn   = w & 3;      // 0..3

    if (tid < 128) {
        scb[tid] = bn[tid] + bw[tid];
        sWw[tid] = Ww[tid];
        sWl[tid] = Wl[tid];
    }

    // Wn B-fragments (bf16) with physical-k quad remap (round-5 proven):
    // physical k quad (ks*16+4lc..+3) -> logical slots {2lc,2lc+1},{2lc+8,2lc+9}.
    uint32_t breg[8][4][2];
#pragma unroll
    for (int ks = 0; ks < 8; ks++)
#pragma unroll
        for (int ni = 0; ni < 4; ni++) {
            const float4 v = *(const float4*)(Wn + (size_t)(wn * 32 + ni * 8 + lg) * 128
                                              + ks * 16 + 4 * lc);
            breg[ks][ni][0] = pack_bf16(v.x, v.y);
            breg[ks][ni][1] = pack_bf16(v.z, v.w);
        }

    const long rowMax = (long)N * 32 - 1;
    const long wMaxQ  = (long)N * 8 - 1;
    const int grid = gridDim.x;

    // ---------- prologue: load tile bid into buffer 0 ----------
    {
        const long r0 = (long)blockIdx.x * 64;
        float4 v[8];
#pragma unroll
        for (int u = 0; u < 8; u++) {
            const int qi = tid + u * 256;
            long gr = r0 + (qi >> 5);
            if (gr > rowMax) gr = rowMax;
            v[u] = __ldg((const float4*)x_nb + gr * 32 + (qi & 31));
        }
#pragma unroll
        for (int u = 0; u < 8; u++) {
            const int qi = tid + u * 256;
            const int row = qi >> 5, c4 = qi & 31;
            uint2 p; p.x = pack_bf16(v[u].x, v[u].y); p.y = pack_bf16(v[u].z, v[u].w);
            *(uint2*)(&sA[0][row * ATS + c4 * 4]) = p;
        }
        if (tid < 64) {
            long node = (long)blockIdx.x * 2 + (tid >> 5); if (node > N - 1) node = N - 1;
            ((float4*)sxs[0])[tid] = __ldg((const float4*)g_xs + node * 32 + (tid & 31));
        } else if (tid < 80) {
            const int j = tid - 64;
            long wi = (long)blockIdx.x * 16 + j; if (wi > wMaxQ) wi = wMaxQ;
            ((float4*)swt[0])[j] = __ldg((const float4*)weight + wi);
        }
    }
    __syncthreads();

    int buf = 0;
    for (int t = blockIdx.x; t < numTiles; t += grid, buf ^= 1) {
        const __nv_bfloat16* A = sA[buf];

        // ---- GEMM: warp M32 x N32, K=128, A LDS.64 (remap), B in regs ----
        float acc[2][4][4];
#pragma unroll
        for (int mi = 0; mi < 2; mi++)
#pragma unroll
            for (int ni = 0; ni < 4; ni++)
#pragma unroll
                for (int j = 0; j < 4; j++) acc[mi][ni][j] = 0.f;

#pragma unroll
        for (int ks = 0; ks < 8; ks++) {
            uint32_t a[2][4];
#pragma unroll
            for (int mi = 0; mi < 2; mi++) {
                const int r = wm * 32 + mi * 16 + lg;
                const uint2 q0 = *(const uint2*)(A + r * ATS + ks * 16 + 4 * lc);
                const uint2 q1 = *(const uint2*)(A + (r + 8) * ATS + ks * 16 + 4 * lc);
                a[mi][0] = q0.x; a[mi][2] = q0.y;
                a[mi][1] = q1.x; a[mi][3] = q1.y;
            }
#pragma unroll
            for (int ni = 0; ni < 4; ni++) {
                mma_bf16(acc[0][ni], a[0], breg[ks][ni]);
                mma_bf16(acc[1][ni], a[1], breg[ks][ni]);
            }
        }

        // ---- scores ----
#pragma unroll
        for (int mi = 0; mi < 2; mi++)
#pragma unroll
            for (int rh = 0; rh < 2; rh++) {
                const int r = wm * 32 + mi * 16 + rh * 8 + lg;
                const int node = r >> 5, k = r & 31;
                const float wgt = swt[buf][node * 32 + k];
                float p = 0.f;
#pragma unroll
                for (int ni = 0; ni < 4; ni++)
#pragma unroll
                    for (int cc = 0; cc < 2; cc++) {
                        const int d = wn * 32 + ni * 8 + 2 * lc + cc;
                        float h = acc[mi][ni][rh * 2 + cc] + sxs[buf][node * 128 + d]
                                + fmaf(wgt, sWw[d], scb[d]);
                        h = fmaxf(h, 0.f) + 0.1f * fminf(h, 0.f);
                        p = fmaf(sWl[d], h, p);
                    }
                p += __shfl_xor_sync(0xffffffffu, p, 1);
                p += __shfl_xor_sync(0xffffffffu, p, 2);
                if (lc == 0) spart[r * 4 + wn] = p;
            }

        // ---- prefetch tile t+grid into registers (acc now dead) ----
        const int tn = t + grid;
        const bool havenext = tn < numTiles;   // uniform
        float4 v[8]; float4 vxs; float4 vwt;
        if (havenext) {
            const long r0 = (long)tn * 64;
#pragma unroll
            for (int u = 0; u < 8; u++) {
                const int qi = tid + u * 256;
                long gr = r0 + (qi >> 5);
                if (gr > rowMax) gr = rowMax;
                v[u] = __ldg((const float4*)x_nb + gr * 32 + (qi & 31));
            }
            if (tid < 64) {
                long node = (long)tn * 2 + (tid >> 5); if (node > N - 1) node = N - 1;
                vxs = __ldg((const float4*)g_xs + node * 32 + (tid & 31));
            } else if (tid < 80) {
                long wi = (long)tn * 16 + (tid - 64); if (wi > wMaxQ) wi = wMaxQ;
                vwt = __ldg((const float4*)weight + wi);
            }
        }

        __syncthreads();   // sync2: spart complete (LDG latency keeps draining)

        // ---- per-warp softmax (node = w>>2, lane = k) ----
        float attn;
        {
            const int node = w >> 2;
            const float4 q = *(const float4*)(spart + (node * 32 + lane) * 4);
            float s = (q.x + q.y) + (q.z + q.w);
            float m = s;
#pragma unroll
            for (int o = 16; o; o >>= 1) m = fmaxf(m, __shfl_xor_sync(0xffffffffu, m, o));
            const float e = expf(s - m);
            float su = e;
#pragma unroll
            for (int o = 16; o; o >>= 1) su += __shfl_xor_sync(0xffffffffu, su, o);
            attn = e / su;   // bl dropped: softmax-invariant
        }

        // ---- output (x_nb rows L1-hot: loaded during previous iteration) ----
        {
            const int node = w >> 2;
            const int d = (w & 3) * 32 + lane;
            const long gn = (long)t * 2 + node;
            if (gn < N) {
                const float* src = x_nb + (gn * 32) * 128 + d;
                float s0 = 0.f, s1 = 0.f;
#pragma unroll
                for (int k = 0; k < 32; k += 2) {
                    const float a0 = __shfl_sync(0xffffffffu, attn, k);
                    const float a1 = __shfl_sync(0xffffffffu, attn, k + 1);
                    s0 = fmaf(a0, __ldg(src + k * 128), s0);
                    s1 = fmaf(a1, __ldg(src + (k + 1) * 128), s1);
                }
                out[gn * 128 + d] = s0 + s1;
            }
        }

        // ---- store prefetched tile into the other buffer ----
        if (havenext) {
            __nv_bfloat16* D = sA[buf ^ 1];
#pragma unroll
            for (int u = 0; u < 8; u++) {
                const int qi = tid + u * 256;
                const int row = qi >> 5, c4 = qi & 31;
                uint2 p; p.x = pack_bf16(v[u].x, v[u].y); p.y = pack_bf16(v[u].z, v[u].w);
                *(uint2*)(&D[row * ATS + c4 * 4]) = p;
            }
            if (tid < 64)       ((float4*)sxs[buf ^ 1])[tid]      = vxs;
            else if (tid < 80)  ((float4*)swt[buf ^ 1])[tid - 64] = vwt;
        }
        __syncthreads();   // syncL: next buffer visible; spart free
    }
}

// ---------------------------------------------------------------------------
extern "C" void kernel_launch(void* const* d_in, const int* in_sizes, int n_in,
                              void* d_out, int out_size)
{
    const float* x      = (const float*)d_in[0];
    const float* x_nb   = (const float*)d_in[1];
    const float* weight = (const float*)d_in[2];
    const float* Wx     = (const float*)d_in[3];
    const float* bx     = (const float*)d_in[4];
    const float* Wn     = (const float*)d_in[5];
    const float* bn     = (const float*)d_in[6];
    const float* Ww     = (const float*)d_in[7];
    const float* bw     = (const float*)d_in[8];
    const float* Wl     = (const float*)d_in[9];
    // d_in[10] = bl: softmax-invariant, unused.
    float* out = (float*)d_out;

    const int N = in_sizes[0] / 128;

    const size_t smem1 = (size_t)(2 * 128 * STX + 128) * sizeof(float);
    cudaFuncSetAttribute(xs_kernel, cudaFuncAttributeMaxDynamicSharedMemorySize, (int)smem1);

    int nSM = 148;
    cudaDeviceGetAttribute(&nSM, cudaDevAttrMultiProcessorCount, 0);

    const int blocks1 = (N + 511) / 512;
    xs_kernel<<<blocks1, 256, smem1>>>(x, Wx, bx, N);

    const int numTiles = (N + 1) / 2;
    int grid = 2 * nSM;
    if (grid > numTiles) grid = numTiles;
    gnn_main_kernel<<<grid, 256>>>(x_nb, weight, Wn, bn, Ww, bw, Wl, out, N, numTiles);
}

// round 8
// speedup vs baseline: 1.2563x; 1.2563x over previous
#include <cuda_runtime.h>
#include <cuda_bf16.h>
#include <cstdint>

#define STX 132      // xs-kernel smem stride (proven)
#define ATS 144      // A/B smem stride in bf16 (288B: conflict-free half-warp LDS.64)

// Scratch for x_s = x @ Wx^T + bx
__device__ float g_xs[65536 * 128];

__device__ __forceinline__ uint32_t f2tf32(float f) {
    uint32_t r; asm volatile("cvt.rna.tf32.f32 %0, %1;" : "=r"(r) : "f"(f)); return r;
}
__device__ __forceinline__ void mma_tf32_frag(float c[4], const uint32_t a[4], const uint32_t b[2]) {
    asm volatile(
        "mma.sync.aligned.m16n8k8.row.col.f32.tf32.tf32.f32 "
        "{%0,%1,%2,%3}, {%4,%5,%6,%7}, {%8,%9}, {%0,%1,%2,%3};"
        : "+f"(c[0]), "+f"(c[1]), "+f"(c[2]), "+f"(c[3])
        : "r"(a[0]), "r"(a[1]), "r"(a[2]), "r"(a[3]), "r"(b[0]), "r"(b[1]));
}
__device__ __forceinline__ void mma_bf16(float c[4], const uint32_t a[4], const uint32_t b[2]) {
    asm volatile(
        "mma.sync.aligned.m16n8k16.row.col.f32.bf16.bf16.f32 "
        "{%0,%1,%2,%3}, {%4,%5,%6,%7}, {%8,%9}, {%0,%1,%2,%3};"
        : "+f"(c[0]), "+f"(c[1]), "+f"(c[2]), "+f"(c[3])
        : "r"(a[0]), "r"(a[1]), "r"(a[2]), "r"(a[3]), "r"(b[0]), "r"(b[1]));
}
__device__ __forceinline__ uint32_t pack_bf16(float lo, float hi) {
    __nv_bfloat162 v = __floats2bfloat162_rn(lo, hi);
    return *reinterpret_cast<uint32_t*>(&v);
}

// ---------------------------------------------------------------------------
// Kernel 1: x_s = x @ Wx^T + bx. 2 tiles per CTA (196 CTAs > 148 SMs; Wx halved).
// ---------------------------------------------------------------------------
__global__ __launch_bounds__(256) void xs_kernel(
    const float* __restrict__ x, const float* __restrict__ Wx,
    const float* __restrict__ bx, int N)
{
    extern __shared__ float smem[];
    float* sW  = smem;
    float* sA  = sW + 128 * STX;
    float* sbx = sA + 128 * STX;
    const int tid = threadIdx.x;

    for (int i = tid; i < 128 * 128; i += 256) {
        int d = i >> 7, e = i & 127;
        ((uint32_t*)sW)[d * STX + e] = f2tf32(Wx[i]);
    }
    if (tid < 128) sbx[tid] = bx[tid];

    const int w = tid >> 5, lane = tid & 31;
    const int lg = lane >> 2, lc = lane & 3;
    const int wm = w >> 1, wn = w & 1;
    const uint32_t* uA = (const uint32_t*)sA;
    const uint32_t* uW = (const uint32_t*)sW;

    for (int s = 0; s < 2; s++) {
        const int tileBase = (blockIdx.x * 2 + s) * 128;
        if (tileBase >= N) break;   // uniform across CTA

        __syncthreads();
        for (int i = tid; i < 128 * 128; i += 256) {
            int r = i >> 7, e = i & 127;
            int node = tileBase + r;
            float v = (node < N) ? x[node * 128 + e] : 0.f;
            ((uint32_t*)sA)[r * STX + e] = f2tf32(v);
        }
        __syncthreads();

        float acc[2][8][4];
#pragma unroll
        for (int mi = 0; mi < 2; mi++)
#pragma unroll
            for (int ni = 0; ni < 8; ni++)
#pragma unroll
                for (int j = 0; j < 4; j++) acc[mi][ni][j] = 0.f;

#pragma unroll 4
        for (int ks = 0; ks < 16; ks++) {
            const int e0 = ks * 8;
            uint32_t afr[2][4];
#pragma unroll
            for (int mi = 0; mi < 2; mi++) {
                int r = wm * 32 + mi * 16 + lg;
                afr[mi][0] = uA[r * STX + e0 + lc];
                afr[mi][1] = uA[(r + 8) * STX + e0 + lc];
                afr[mi][2] = uA[r * STX + e0 + 4 + lc];
                afr[mi][3] = uA[(r + 8) * STX + e0 + 4 + lc];
            }
#pragma unroll
            for (int ni = 0; ni < 8; ni++) {
                int c0 = wn * 64 + ni * 8;
                uint32_t bfr[2];
                bfr[0] = uW[(c0 + lg) * STX + e0 + lc];
                bfr[1] = uW[(c0 + lg) * STX + e0 + 4 + lc];
                mma_tf32_frag(acc[0][ni], afr[0], bfr);
                mma_tf32_frag(acc[1][ni], afr[1], bfr);
            }
        }
#pragma unroll
        for (int mi = 0; mi < 2; mi++)
#pragma unroll
            for (int rh = 0; rh < 2; rh++) {
                int r = wm * 32 + mi * 16 + rh * 8 + lg;
                int node = tileBase + r;
                if (node < N) {
#pragma unroll
                    for (int ni = 0; ni < 8; ni++)
#pragma unroll
                        for (int cc = 0; cc < 2; cc++) {
                            int d = wn * 64 + ni * 8 + 2 * lc + cc;
                            g_xs[node * 128 + d] = acc[mi][ni][rh * 2 + cc] + sbx[d];
                        }
                }
            }
    }
}

// ---------------------------------------------------------------------------
// Main kernel: round-5 structure, but Wn in smem as bf16 (loaded once per
// persistent CTA) -> 64 regs freed -> 3 CTAs/SM (24 warps). B fragments are
// single LDS.64 with the same physical-k-quad remap as A (proven in R5).
// Dynamic smem ~58KB/CTA.
// ---------------------------------------------------------------------------
#define SA_BYTES 18432           // 64*144*2
#define SB_BYTES 36864           // 128*144*2

__global__ __launch_bounds__(256, 3) void gnn_main_kernel(
    const float* __restrict__ x_nb, const float* __restrict__ weight,
    const float* __restrict__ Wn, const float* __restrict__ bn,
    const float* __restrict__ Ww, const float* __restrict__ bw,
    const float* __restrict__ Wl,
    float* __restrict__ out, int N, int numTiles)
{
    extern __shared__ char dsm[];
    __nv_bfloat16* sA = (__nv_bfloat16*)dsm;                       // 64 x ATS
    __nv_bfloat16* sB = (__nv_bfloat16*)(dsm + SA_BYTES);          // 128 x ATS
    float* sxs   = (float*)(dsm + SA_BYTES + SB_BYTES);            // 256
    float* swt   = sxs + 256;     // 64
    float* spart = swt + 64;      // 256
    float* sattn = spart + 256;   // 64
    float* scb   = sattn + 64;    // 128
    float* sWw   = scb + 128;     // 128
    float* sWl   = sWw + 128;     // 128

    const int tid  = threadIdx.x;
    const int w    = tid >> 5, lane = tid & 31;
    const int lg   = lane >> 2, lc = lane & 3;
    const int wm   = w >> 2;     // 0..1
    const int wn   = w & 3;      // 0..3

    if (tid < 128) {
        scb[tid] = bn[tid] + bw[tid];
        sWw[tid] = Ww[tid];
        sWl[tid] = Wl[tid];
    }
    // One-time Wn -> smem bf16 (row n, stride ATS). float2 -> bf16x2 stores.
    for (int i = tid; i < 128 * 64; i += 256) {
        const int n = i >> 6, k2 = i & 63;
        const float2 v = ((const float2*)Wn)[i];
        *(uint32_t*)(sB + n * ATS + k2 * 2) = pack_bf16(v.x, v.y);
    }

    const long rowMax = (long)N * 32 - 1;
    const long wMaxQ  = (long)N * 8 - 1;
    const int grid = gridDim.x;

    for (int t = blockIdx.x; t < numTiles; t += grid) {
        __syncthreads();   // smem reuse fence (also covers sB init on iter 0)

        // ---- load tile: 64 rows x 128 fp32 -> bf16 smem ----
        {
            float4 v[8];
            const long r0 = (long)t * 64;
#pragma unroll
            for (int u = 0; u < 8; u++) {
                const int qi = tid + u * 256;
                long gr = r0 + (qi >> 5);
                if (gr > rowMax) gr = rowMax;
                v[u] = __ldg((const float4*)x_nb + gr * 32 + (qi & 31));
            }
#pragma unroll
            for (int u = 0; u < 8; u++) {
                const int qi = tid + u * 256;
                const int row = qi >> 5, c4 = qi & 31;
                uint2 p; p.x = pack_bf16(v[u].x, v[u].y); p.y = pack_bf16(v[u].z, v[u].w);
                *(uint2*)(sA + row * ATS + c4 * 4) = p;
            }
            if (tid < 64) {
                long node = (long)t * 2 + (tid >> 5); if (node > N - 1) node = N - 1;
                ((float4*)sxs)[tid] = __ldg((const float4*)g_xs + node * 32 + (tid & 31));
            } else if (tid < 80) {
                const int j = tid - 64;
                long wi = (long)t * 16 + j; if (wi > wMaxQ) wi = wMaxQ;
                ((float4*)swt)[j] = __ldg((const float4*)weight + wi);
            }
        }
        __syncthreads();

        // ---- GEMM: warp M32 x N32, K=128, A and B via LDS.64 (k-quad remap) ----
        float acc[2][4][4];
#pragma unroll
        for (int mi = 0; mi < 2; mi++)
#pragma unroll
            for (int ni = 0; ni < 4; ni++)
#pragma unroll
                for (int j = 0; j < 4; j++) acc[mi][ni][j] = 0.f;

#pragma unroll
        for (int ks = 0; ks < 8; ks++) {
            const int e = ks * 16 + 4 * lc;
            uint32_t a[2][4];
#pragma unroll
            for (int mi = 0; mi < 2; mi++) {
                const int r = wm * 32 + mi * 16 + lg;
                const uint2 q0 = *(const uint2*)(sA + r * ATS + e);
                const uint2 q1 = *(const uint2*)(sA + (r + 8) * ATS + e);
                a[mi][0] = q0.x; a[mi][2] = q0.y;
                a[mi][1] = q1.x; a[mi][3] = q1.y;
            }
#pragma unroll
            for (int ni = 0; ni < 4; ni++) {
                const uint2 qb = *(const uint2*)(sB + (wn * 32 + ni * 8 + lg) * ATS + e);
                uint32_t b[2] = {qb.x, qb.y};
                mma_bf16(acc[0][ni], a[0], b);
                mma_bf16(acc[1][ni], a[1], b);
            }
        }

        // ---- scores: h = n_s + x_s + (bn+bw) + weight*Ww ; leaky(0.1) ; dot Wl ----
#pragma unroll
        for (int mi = 0; mi < 2; mi++)
#pragma unroll
            for (int rh = 0; rh < 2; rh++) {
                const int r = wm * 32 + mi * 16 + rh * 8 + lg;   // 0..63
                const int node = r >> 5, k = r & 31;
                const float wgt = swt[node * 32 + k];
                float p = 0.f;
#pragma unroll
                for (int ni = 0; ni < 4; ni++)
#pragma unroll
                    for (int cc = 0; cc < 2; cc++) {
                        const int d = wn * 32 + ni * 8 + 2 * lc + cc;
                        float h = acc[mi][ni][rh * 2 + cc] + sxs[node * 128 + d]
                                + fmaf(wgt, sWw[d], scb[d]);
                        h = fmaxf(h, 0.f) + 0.1f * fminf(h, 0.f);
                        p = fmaf(sWl[d], h, p);
                    }
                p += __shfl_xor_sync(0xffffffffu, p, 1);
                p += __shfl_xor_sync(0xffffffffu, p, 2);
                if (lc == 0) spart[r * 4 + wn] = p;
            }
        __syncthreads();

        // ---- softmax over K=32 per node (bl dropped: softmax-invariant) ----
        if (w < 2) {
            const int r = w * 32 + lane;    // node = w, k = lane
            float s = spart[r * 4] + spart[r * 4 + 1] + spart[r * 4 + 2] + spart[r * 4 + 3];
            float m = s;
#pragma unroll
            for (int o = 16; o; o >>= 1) m = fmaxf(m, __shfl_xor_sync(0xffffffffu, m, o));
            float e = expf(s - m);
            float su = e;
#pragma unroll
            for (int o = 16; o; o >>= 1) su += __shfl_xor_sync(0xffffffffu, su, o);
            sattn[r] = e / su;
        }
        __syncthreads();

        // ---- output: out[n,d] = sum_k attn[k] * x_nb[n,k,d]  (fp32, L1-hot) ----
        {
            const int node = tid >> 7, d = tid & 127;
            const long gn = (long)t * 2 + node;
            if (gn < N) {
                const float* src = x_nb + (gn * 32) * 128 + d;
                const float* at  = sattn + node * 32;
                float s0 = 0.f, s1 = 0.f;
#pragma unroll
                for (int k = 0; k < 32; k += 2) {
                    s0 = fmaf(at[k],     __ldg(src + k * 128),       s0);
                    s1 = fmaf(at[k + 1], __ldg(src + (k + 1) * 128), s1);
                }
                out[gn * 128 + d] = s0 + s1;
            }
        }
    }
}

// ---------------------------------------------------------------------------
extern "C" void kernel_launch(void* const* d_in, const int* in_sizes, int n_in,
                              void* d_out, int out_size)
{
    const float* x      = (const float*)d_in[0];
    const float* x_nb   = (const float*)d_in[1];
    const float* weight = (const float*)d_in[2];
    const float* Wx     = (const float*)d_in[3];
    const float* bx     = (const float*)d_in[4];
    const float* Wn     = (const float*)d_in[5];
    const float* bn     = (const float*)d_in[6];
    const float* Ww     = (const float*)d_in[7];
    const float* bw     = (const float*)d_in[8];
    const float* Wl     = (const float*)d_in[9];
    // d_in[10] = bl: softmax-invariant, unused.
    float* out = (float*)d_out;

    const int N = in_sizes[0] / 128;

    const size_t smem1 = (size_t)(2 * 128 * STX + 128) * sizeof(float);
    cudaFuncSetAttribute(xs_kernel, cudaFuncAttributeMaxDynamicSharedMemorySize, (int)smem1);

    const size_t smem2 = SA_BYTES + SB_BYTES
                       + (256 + 64 + 256 + 64 + 128 + 128 + 128) * sizeof(float);
    cudaFuncSetAttribute(gnn_main_kernel, cudaFuncAttributeMaxDynamicSharedMemorySize, (int)smem2);

    int nSM = 148;
    cudaDeviceGetAttribute(&nSM, cudaDevAttrMultiProcessorCount, 0);

    const int blocks1 = (N + 255) / 256;
    xs_kernel<<<blocks1, 256, smem1>>>(x, Wx, bx, N);

    const int numTiles = (N + 1) / 2;
    int grid = 3 * nSM;
    if (grid > numTiles) grid = numTiles;
    gnn_main_kernel<<<grid, 256, smem2>>>(x_nb, weight, Wn, bn, Ww, bw, Wl, out, N, numTiles);
}

// round 10
// speedup vs baseline: 1.2592x; 1.0023x over previous
#include <cuda_runtime.h>
#include <cuda_bf16.h>
#include <cstdint>

#define STX 132      // xs-kernel smem stride (proven)
#define ATS 144      // A/B smem stride in bf16 (288B: conflict-free half-warp LDS.64)

// Scratch for x_s = x @ Wx^T + bx
__device__ float g_xs[65536 * 128];

__device__ __forceinline__ uint32_t f2tf32(float f) {
    uint32_t r; asm volatile("cvt.rna.tf32.f32 %0, %1;" : "=r"(r) : "f"(f)); return r;
}
__device__ __forceinline__ void mma_tf32_frag(float c[4], const uint32_t a[4], const uint32_t b[2]) {
    asm volatile(
        "mma.sync.aligned.m16n8k8.row.col.f32.tf32.tf32.f32 "
        "{%0,%1,%2,%3}, {%4,%5,%6,%7}, {%8,%9}, {%0,%1,%2,%3};"
        : "+f"(c[0]), "+f"(c[1]), "+f"(c[2]), "+f"(c[3])
        : "r"(a[0]), "r"(a[1]), "r"(a[2]), "r"(a[3]), "r"(b[0]), "r"(b[1]));
}
__device__ __forceinline__ void mma_bf16(float c[4], const uint32_t a[4], const uint32_t b[2]) {
    asm volatile(
        "mma.sync.aligned.m16n8k16.row.col.f32.bf16.bf16.f32 "
        "{%0,%1,%2,%3}, {%4,%5,%6,%7}, {%8,%9}, {%0,%1,%2,%3};"
        : "+f"(c[0]), "+f"(c[1]), "+f"(c[2]), "+f"(c[3])
        : "r"(a[0]), "r"(a[1]), "r"(a[2]), "r"(a[3]), "r"(b[0]), "r"(b[1]));
}
__device__ __forceinline__ uint32_t pack_bf16(float lo, float hi) {
    __nv_bfloat162 v = __floats2bfloat162_rn(lo, hi);
    return *reinterpret_cast<uint32_t*>(&v);
}

// ---------------------------------------------------------------------------
// Kernel 1: x_s = x @ Wx^T + bx. 2 tiles per CTA (196 CTAs; Wx loads halved).
// ---------------------------------------------------------------------------
__global__ __launch_bounds__(256) void xs_kernel(
    const float* __restrict__ x, const float* __restrict__ Wx,
    const float* __restrict__ bx, int N)
{
    extern __shared__ float smem[];
    float* sW  = smem;
    float* sA  = sW + 128 * STX;
    float* sbx = sA + 128 * STX;
    const int tid = threadIdx.x;

    for (int i = tid; i < 128 * 128; i += 256) {
        int d = i >> 7, e = i & 127;
        ((uint32_t*)sW)[d * STX + e] = f2tf32(Wx[i]);
    }
    if (tid < 128) sbx[tid] = bx[tid];

    const int w = tid >> 5, lane = tid & 31;
    const int lg = lane >> 2, lc = lane & 3;
    const int wm = w >> 1, wn = w & 1;
    const uint32_t* uA = (const uint32_t*)sA;
    const uint32_t* uW = (const uint32_t*)sW;

    for (int s = 0; s < 2; s++) {
        const int tileBase = (blockIdx.x * 2 + s) * 128;
        if (tileBase >= N) break;   // uniform across CTA

        __syncthreads();
        for (int i = tid; i < 128 * 128; i += 256) {
            int r = i >> 7, e = i & 127;
            int node = tileBase + r;
            float v = (node < N) ? x[node * 128 + e] : 0.f;
            ((uint32_t*)sA)[r * STX + e] = f2tf32(v);
        }
        __syncthreads();

        float acc[2][8][4];
#pragma unroll
        for (int mi = 0; mi < 2; mi++)
#pragma unroll
            for (int ni = 0; ni < 8; ni++)
#pragma unroll
                for (int j = 0; j < 4; j++) acc[mi][ni][j] = 0.f;

#pragma unroll 4
        for (int ks = 0; ks < 16; ks++) {
            const int e0 = ks * 8;
            uint32_t afr[2][4];
#pragma unroll
            for (int mi = 0; mi < 2; mi++) {
                int r = wm * 32 + mi * 16 + lg;
                afr[mi][0] = uA[r * STX + e0 + lc];
                afr[mi][1] = uA[(r + 8) * STX + e0 + lc];
                afr[mi][2] = uA[r * STX + e0 + 4 + lc];
                afr[mi][3] = uA[(r + 8) * STX + e0 + 4 + lc];
            }
#pragma unroll
            for (int ni = 0; ni < 8; ni++) {
                int c0 = wn * 64 + ni * 8;
                uint32_t bfr[2];
                bfr[0] = uW[(c0 + lg) * STX + e0 + lc];
                bfr[1] = uW[(c0 + lg) * STX + e0 + 4 + lc];
                mma_tf32_frag(acc[0][ni], afr[0], bfr);
                mma_tf32_frag(acc[1][ni], afr[1], bfr);
            }
        }
#pragma unroll
        for (int mi = 0; mi < 2; mi++)
#pragma unroll
            for (int rh = 0; rh < 2; rh++) {
                int r = wm * 32 + mi * 16 + rh * 8 + lg;
                int node = tileBase + r;
                if (node < N) {
#pragma unroll
                    for (int ni = 0; ni < 8; ni++)
#pragma unroll
                        for (int cc = 0; cc < 2; cc++) {
                            int d = wn * 64 + ni * 8 + 2 * lc + cc;
                            g_xs[node * 128 + d] = acc[mi][ni][rh * 2 + cc] + sbx[d];
                        }
                }
            }
    }
}

// ---------------------------------------------------------------------------
// Main kernel: Wn in smem bf16 (loaded once per persistent CTA), 3 CTAs/SM
// (24 warps). B frags = single LDS.64 with the same physical-k-quad remap as
// A (proven R5/R8). 3 barriers per tile (top-of-loop fence proven redundant:
// post-scores barrier orders sA/sxs/swt reads before next-tile writes;
// post-softmax barrier orders sattn).
// ---------------------------------------------------------------------------
#define SA_BYTES 18432           // 64*144*2
#define SB_BYTES 36864           // 128*144*2

__global__ __launch_bounds__(256, 3) void gnn_main_kernel(
    const float* __restrict__ x_nb, const float* __restrict__ weight,
    const float* __restrict__ Wn, const float* __restrict__ bn,
    const float* __restrict__ Ww, const float* __restrict__ bw,
    const float* __restrict__ Wl,
    float* __restrict__ out, int N, int numTiles)
{
    extern __shared__ char dsm[];
    __nv_bfloat16* sA = (__nv_bfloat16*)dsm;                       // 64 x ATS
    __nv_bfloat16* sB = (__nv_bfloat16*)(dsm + SA_BYTES);          // 128 x ATS
    float* sxs   = (float*)(dsm + SA_BYTES + SB_BYTES);            // 256
    float* swt   = sxs + 256;     // 64
    float* spart = swt + 64;      // 256
    float* sattn = spart + 256;   // 64
    float* scb   = sattn + 64;    // 128
    float* sWw   = scb + 128;     // 128
    float* sWl   = sWw + 128;     // 128

    const int tid  = threadIdx.x;
    const int w    = tid >> 5, lane = tid & 31;
    const int lg   = lane >> 2, lc = lane & 3;
    const int wm   = w >> 2;     // 0..1
    const int wn   = w & 3;      // 0..3

    if (tid < 128) {
        scb[tid] = bn[tid] + bw[tid];
        sWw[tid] = Ww[tid];
        sWl[tid] = Wl[tid];
    }
    // One-time Wn -> smem bf16 (row n, stride ATS). Ordered by the post-load
    // barrier of the first iteration.
    for (int i = tid; i < 128 * 64; i += 256) {
        const int n = i >> 6, k2 = i & 63;
        const float2 v = ((const float2*)Wn)[i];
        *(uint32_t*)(sB + n * ATS + k2 * 2) = pack_bf16(v.x, v.y);
    }

    const long rowMax = (long)N * 32 - 1;
    const long wMaxQ  = (long)N * 8 - 1;
    const int grid = gridDim.x;

    for (int t = blockIdx.x; t < numTiles; t += grid) {
        // ---- load tile: 64 rows x 128 fp32 -> bf16 smem ----
        // (Safe without a leading barrier: previous tile's sA/sxs/swt readers
        //  all precede the post-scores barrier of that tile.)
        {
            float4 v[8];
            const long r0 = (long)t * 64;
#pragma unroll
            for (int u = 0; u < 8; u++) {
                const int qi = tid + u * 256;
                long gr = r0 + (qi >> 5);
                if (gr > rowMax) gr = rowMax;
                v[u] = __ldg((const float4*)x_nb + gr * 32 + (qi & 31));
            }
#pragma unroll
            for (int u = 0; u < 8; u++) {
                const int qi = tid + u * 256;
                const int row = qi >> 5, c4 = qi & 31;
                uint2 p; p.x = pack_bf16(v[u].x, v[u].y); p.y = pack_bf16(v[u].z, v[u].w);
                *(uint2*)(sA + row * ATS + c4 * 4) = p;
            }
            if (tid < 64) {
                long node = (long)t * 2 + (tid >> 5); if (node > N - 1) node = N - 1;
                ((float4*)sxs)[tid] = __ldg((const float4*)g_xs + node * 32 + (tid & 31));
            } else if (tid < 80) {
                const int j = tid - 64;
                long wi = (long)t * 16 + j; if (wi > wMaxQ) wi = wMaxQ;
                ((float4*)swt)[j] = __ldg((const float4*)weight + wi);
            }
        }
        __syncthreads();   // sync1: tile (and iter-0 sB/constants) visible

        // ---- GEMM: warp M32 x N32, K=128, A and B via LDS.64 (k-quad remap) ----
        float acc[2][4][4];
#pragma unroll
        for (int mi = 0; mi < 2; mi++)
#pragma unroll
            for (int ni = 0; ni < 4; ni++)
#pragma unroll
                for (int j = 0; j < 4; j++) acc[mi][ni][j] = 0.f;

#pragma unroll
        for (int ks = 0; ks < 8; ks++) {
            const int e = ks * 16 + 4 * lc;
            uint32_t a[2][4];
#pragma unroll
            for (int mi = 0; mi < 2; mi++) {
                const int r = wm * 32 + mi * 16 + lg;
                const uint2 q0 = *(const uint2*)(sA + r * ATS + e);
                const uint2 q1 = *(const uint2*)(sA + (r + 8) * ATS + e);
                a[mi][0] = q0.x; a[mi][2] = q0.y;
                a[mi][1] = q1.x; a[mi][3] = q1.y;
            }
#pragma unroll
            for (int ni = 0; ni < 4; ni++) {
                const uint2 qb = *(const uint2*)(sB + (wn * 32 + ni * 8 + lg) * ATS + e);
                uint32_t b[2] = {qb.x, qb.y};
                mma_bf16(acc[0][ni], a[0], b);
                mma_bf16(acc[1][ni], a[1], b);
            }
        }

        // ---- scores: h = n_s + x_s + (bn+bw) + weight*Ww ; leaky(0.1) ; dot Wl ----
#pragma unroll
        for (int mi = 0; mi < 2; mi++)
#pragma unroll
            for (int rh = 0; rh < 2; rh++) {
                const int r = wm * 32 + mi * 16 + rh * 8 + lg;   // 0..63
                const int node = r >> 5, k = r & 31;
                const float wgt = swt[node * 32 + k];
                float p = 0.f;
#pragma unroll
                for (int ni = 0; ni < 4; ni++)
#pragma unroll
                    for (int cc = 0; cc < 2; cc++) {
                        const int d = wn * 32 + ni * 8 + 2 * lc + cc;
                        float h = acc[mi][ni][rh * 2 + cc] + sxs[node * 128 + d]
                                + fmaf(wgt, sWw[d], scb[d]);
                        h = fmaxf(h, 0.f) + 0.1f * fminf(h, 0.f);
                        p = fmaf(sWl[d], h, p);
                    }
                p += __shfl_xor_sync(0xffffffffu, p, 1);
                p += __shfl_xor_sync(0xffffffffu, p, 2);
                if (lc == 0) spart[r * 4 + wn] = p;
            }
        __syncthreads();   // sync2: spart ready; sA/sxs/swt reads complete

        // ---- softmax over K=32 per node (bl dropped: softmax-invariant) ----
        if (w < 2) {
            const int r = w * 32 + lane;    // node = w, k = lane
            float s = spart[r * 4] + spart[r * 4 + 1] + spart[r * 4 + 2] + spart[r * 4 + 3];
            float m = s;
#pragma unroll
            for (int o = 16; o; o >>= 1) m = fmaxf(m, __shfl_xor_sync(0xffffffffu, m, o));
            float e = expf(s - m);
            float su = e;
#pragma unroll
            for (int o = 16; o; o >>= 1) su += __shfl_xor_sync(0xffffffffu, su, o);
            sattn[r] = e / su;
        }
        __syncthreads();   // sync3: sattn ready; spart reads complete

        // ---- output: out[n,d] = sum_k attn[k] * x_nb[n,k,d]  (fp32, L1-hot) ----
        {
            const int node = tid >> 7, d = tid & 127;
            const long gn = (long)t * 2 + node;
            if (gn < N) {
                const float* src = x_nb + (gn * 32) * 128 + d;
                const float* at  = sattn + node * 32;
                float s0 = 0.f, s1 = 0.f;
#pragma unroll
                for (int k = 0; k < 32; k += 2) {
                    s0 = fmaf(at[k],     __ldg(src + k * 128),       s0);
                    s1 = fmaf(at[k + 1], __ldg(src + (k + 1) * 128), s1);
                }
                out[gn * 128 + d] = s0 + s1;
            }
        }
    }
}

// ---------------------------------------------------------------------------
extern "C" void kernel_launch(void* const* d_in, const int* in_sizes, int n_in,
                              void* d_out, int out_size)
{
    const float* x      = (const float*)d_in[0];
    const float* x_nb   = (const float*)d_in[1];
    const float* weight = (const float*)d_in[2];
    const float* Wx     = (const float*)d_in[3];
    const float* bx     = (const float*)d_in[4];
    const float* Wn     = (const float*)d_in[5];
    const float* bn     = (const float*)d_in[6];
    const float* Ww     = (const float*)d_in[7];
    const float* bw     = (const float*)d_in[8];
    const float* Wl     = (const float*)d_in[9];
    // d_in[10] = bl: softmax-invariant, unused.
    float* out = (float*)d_out;

    const int N = in_sizes[0] / 128;

    const size_t smem1 = (size_t)(2 * 128 * STX + 128) * sizeof(float);
    cudaFuncSetAttribute(xs_kernel, cudaFuncAttributeMaxDynamicSharedMemorySize, (int)smem1);

    const size_t smem2 = SA_BYTES + SB_BYTES
                       + (256 + 64 + 256 + 64 + 128 + 128 + 128) * sizeof(float);
    cudaFuncSetAttribute(gnn_main_kernel, cudaFuncAttributeMaxDynamicSharedMemorySize, (int)smem2);

    int nSM = 148;
    cudaDeviceGetAttribute(&nSM, cudaDevAttrMultiProcessorCount, 0);

    const int blocks1 = (N + 255) / 256;
    xs_kernel<<<blocks1, 256, smem1>>>(x, Wx, bx, N);

    const int numTiles = (N + 1) / 2;
    int grid = 3 * nSM;
    if (grid > numTiles) grid = numTiles;
    gnn_main_kernel<<<grid, 256, smem2>>>(x_nb, weight, Wn, bn, Ww, bw, Wl, out, N, numTiles);
}

// round 11
// speedup vs baseline: 1.3428x; 1.0663x over previous
#include <cuda_runtime.h>
#include <cuda_bf16.h>
#include <cstdint>

#define STX 132      // xs-kernel smem stride (proven)
#define ATS 144      // A/B smem stride in bf16 (288B: conflict-free half-warp LDS.64)

// Scratch for x_s = x @ Wx^T + bx
__device__ float g_xs[65536 * 128];

__device__ __forceinline__ uint32_t f2tf32(float f) {
    uint32_t r; asm volatile("cvt.rna.tf32.f32 %0, %1;" : "=r"(r) : "f"(f)); return r;
}
__device__ __forceinline__ void mma_tf32_frag(float c[4], const uint32_t a[4], const uint32_t b[2]) {
    asm volatile(
        "mma.sync.aligned.m16n8k8.row.col.f32.tf32.tf32.f32 "
        "{%0,%1,%2,%3}, {%4,%5,%6,%7}, {%8,%9}, {%0,%1,%2,%3};"
        : "+f"(c[0]), "+f"(c[1]), "+f"(c[2]), "+f"(c[3])
        : "r"(a[0]), "r"(a[1]), "r"(a[2]), "r"(a[3]), "r"(b[0]), "r"(b[1]));
}
__device__ __forceinline__ void mma_bf16(float c[4], const uint32_t a[4], const uint32_t b[2]) {
    asm volatile(
        "mma.sync.aligned.m16n8k16.row.col.f32.bf16.bf16.f32 "
        "{%0,%1,%2,%3}, {%4,%5,%6,%7}, {%8,%9}, {%0,%1,%2,%3};"
        : "+f"(c[0]), "+f"(c[1]), "+f"(c[2]), "+f"(c[3])
        : "r"(a[0]), "r"(a[1]), "r"(a[2]), "r"(a[3]), "r"(b[0]), "r"(b[1]));
}
__device__ __forceinline__ uint32_t pack_bf16(float lo, float hi) {
    __nv_bfloat162 v = __floats2bfloat162_rn(lo, hi);
    return *reinterpret_cast<uint32_t*>(&v);
}

// ---------------------------------------------------------------------------
// Kernel 1: x_s = x @ Wx^T + bx  (tf32, bit-identical math to prior rounds).
// Restructured for occupancy: M64 x N128 per CTA -> 99.5KB smem -> 2 CTAs/SM,
// 782 CTAs (was 196 at 1 CTA/SM). Wx re-reads are L2-resident.
// ---------------------------------------------------------------------------
__global__ __launch_bounds__(256, 2) void xs_kernel(
    const float* __restrict__ x, const float* __restrict__ Wx,
    const float* __restrict__ bx, int N)
{
    extern __shared__ float smem[];
    float* sW  = smem;                    // 128 x STX (tf32 bits)
    float* sA  = sW + 128 * STX;          // 64 x STX (tf32 bits)
    float* sbx = sA + 64 * STX;           // 128
    const int tid = threadIdx.x;
    const int tileBase = blockIdx.x * 64;

    for (int i = tid; i < 128 * 128; i += 256) {
        int d = i >> 7, e = i & 127;
        ((uint32_t*)sW)[d * STX + e] = f2tf32(Wx[i]);
    }
    for (int i = tid; i < 64 * 128; i += 256) {
        int r = i >> 7, e = i & 127;
        int node = tileBase + r;
        float v = (node < N) ? x[node * 128 + e] : 0.f;
        ((uint32_t*)sA)[r * STX + e] = f2tf32(v);
    }
    if (tid < 128) sbx[tid] = bx[tid];
    __syncthreads();

    const int w = tid >> 5, lane = tid & 31;
    const int lg = lane >> 2, lc = lane & 3;
    const int wm = w >> 2;    // 0..1 : M32 block
    const int wn = w & 3;     // 0..3 : N32 block

    float acc[2][4][4];
#pragma unroll
    for (int mi = 0; mi < 2; mi++)
#pragma unroll
        for (int ni = 0; ni < 4; ni++)
#pragma unroll
            for (int j = 0; j < 4; j++) acc[mi][ni][j] = 0.f;

    const uint32_t* uA = (const uint32_t*)sA;
    const uint32_t* uW = (const uint32_t*)sW;
#pragma unroll 4
    for (int ks = 0; ks < 16; ks++) {
        const int e0 = ks * 8;
        uint32_t afr[2][4];
#pragma unroll
        for (int mi = 0; mi < 2; mi++) {
            int r = wm * 32 + mi * 16 + lg;
            afr[mi][0] = uA[r * STX + e0 + lc];
            afr[mi][1] = uA[(r + 8) * STX + e0 + lc];
            afr[mi][2] = uA[r * STX + e0 + 4 + lc];
            afr[mi][3] = uA[(r + 8) * STX + e0 + 4 + lc];
        }
#pragma unroll
        for (int ni = 0; ni < 4; ni++) {
            int c0 = wn * 32 + ni * 8;
            uint32_t bfr[2];
            bfr[0] = uW[(c0 + lg) * STX + e0 + lc];
            bfr[1] = uW[(c0 + lg) * STX + e0 + 4 + lc];
            mma_tf32_frag(acc[0][ni], afr[0], bfr);
            mma_tf32_frag(acc[1][ni], afr[1], bfr);
        }
    }
#pragma unroll
    for (int mi = 0; mi < 2; mi++)
#pragma unroll
        for (int rh = 0; rh < 2; rh++) {
            int r = wm * 32 + mi * 16 + rh * 8 + lg;
            int node = tileBase + r;
            if (node < N) {
#pragma unroll
                for (int ni = 0; ni < 4; ni++)
#pragma unroll
                    for (int cc = 0; cc < 2; cc++) {
                        int d = wn * 32 + ni * 8 + 2 * lc + cc;
                        g_xs[node * 128 + d] = acc[mi][ni][rh * 2 + cc] + sbx[d];
                    }
            }
        }
}

// ---------------------------------------------------------------------------
// Main kernel: UNCHANGED from round 10 (best: 361.5us, 3 CTAs/SM).
// Wn in smem bf16; B frags single LDS.64 with physical-k-quad remap;
// 3 barriers/tile.
// ---------------------------------------------------------------------------
#define SA_BYTES 18432           // 64*144*2
#define SB_BYTES 36864           // 128*144*2

__global__ __launch_bounds__(256, 3) void gnn_main_kernel(
    const float* __restrict__ x_nb, const float* __restrict__ weight,
    const float* __restrict__ Wn, const float* __restrict__ bn,
    const float* __restrict__ Ww, const float* __restrict__ bw,
    const float* __restrict__ Wl,
    float* __restrict__ out, int N, int numTiles)
{
    extern __shared__ char dsm[];
    __nv_bfloat16* sA = (__nv_bfloat16*)dsm;                       // 64 x ATS
    __nv_bfloat16* sB = (__nv_bfloat16*)(dsm + SA_BYTES);          // 128 x ATS
    float* sxs   = (float*)(dsm + SA_BYTES + SB_BYTES);            // 256
    float* swt   = sxs + 256;     // 64
    float* spart = swt + 64;      // 256
    float* sattn = spart + 256;   // 64
    float* scb   = sattn + 64;    // 128
    float* sWw   = scb + 128;     // 128
    float* sWl   = sWw + 128;     // 128

    const int tid  = threadIdx.x;
    const int w    = tid >> 5, lane = tid & 31;
    const int lg   = lane >> 2, lc = lane & 3;
    const int wm   = w >> 2;     // 0..1
    const int wn   = w & 3;      // 0..3

    if (tid < 128) {
        scb[tid] = bn[tid] + bw[tid];
        sWw[tid] = Ww[tid];
        sWl[tid] = Wl[tid];
    }
    // One-time Wn -> smem bf16 (row n, stride ATS).
    for (int i = tid; i < 128 * 64; i += 256) {
        const int n = i >> 6, k2 = i & 63;
        const float2 v = ((const float2*)Wn)[i];
        *(uint32_t*)(sB + n * ATS + k2 * 2) = pack_bf16(v.x, v.y);
    }

    const long rowMax = (long)N * 32 - 1;
    const long wMaxQ  = (long)N * 8 - 1;
    const int grid = gridDim.x;

    for (int t = blockIdx.x; t < numTiles; t += grid) {
        // ---- load tile: 64 rows x 128 fp32 -> bf16 smem ----
        {
            float4 v[8];
            const long r0 = (long)t * 64;
#pragma unroll
            for (int u = 0; u < 8; u++) {
                const int qi = tid + u * 256;
                long gr = r0 + (qi >> 5);
                if (gr > rowMax) gr = rowMax;
                v[u] = __ldg((const float4*)x_nb + gr * 32 + (qi & 31));
            }
#pragma unroll
            for (int u = 0; u < 8; u++) {
                const int qi = tid + u * 256;
                const int row = qi >> 5, c4 = qi & 31;
                uint2 p; p.x = pack_bf16(v[u].x, v[u].y); p.y = pack_bf16(v[u].z, v[u].w);
                *(uint2*)(sA + row * ATS + c4 * 4) = p;
            }
            if (tid < 64) {
                long node = (long)t * 2 + (tid >> 5); if (node > N - 1) node = N - 1;
                ((float4*)sxs)[tid] = __ldg((const float4*)g_xs + node * 32 + (tid & 31));
            } else if (tid < 80) {
                const int j = tid - 64;
                long wi = (long)t * 16 + j; if (wi > wMaxQ) wi = wMaxQ;
                ((float4*)swt)[j] = __ldg((const float4*)weight + wi);
            }
        }
        __syncthreads();   // sync1: tile (and iter-0 sB/constants) visible

        // ---- GEMM: warp M32 x N32, K=128, A and B via LDS.64 (k-quad remap) ----
        float acc[2][4][4];
#pragma unroll
        for (int mi = 0; mi < 2; mi++)
#pragma unroll
            for (int ni = 0; ni < 4; ni++)
#pragma unroll
                for (int j = 0; j < 4; j++) acc[mi][ni][j] = 0.f;

#pragma unroll
        for (int ks = 0; ks < 8; ks++) {
            const int e = ks * 16 + 4 * lc;
            uint32_t a[2][4];
#pragma unroll
            for (int mi = 0; mi < 2; mi++) {
                const int r = wm * 32 + mi * 16 + lg;
                const uint2 q0 = *(const uint2*)(sA + r * ATS + e);
                const uint2 q1 = *(const uint2*)(sA + (r + 8) * ATS + e);
                a[mi][0] = q0.x; a[mi][2] = q0.y;
                a[mi][1] = q1.x; a[mi][3] = q1.y;
            }
#pragma unroll
            for (int ni = 0; ni < 4; ni++) {
                const uint2 qb = *(const uint2*)(sB + (wn * 32 + ni * 8 + lg) * ATS + e);
                uint32_t b[2] = {qb.x, qb.y};
                mma_bf16(acc[0][ni], a[0], b);
                mma_bf16(acc[1][ni], a[1], b);
            }
        }

        // ---- scores: h = n_s + x_s + (bn+bw) + weight*Ww ; leaky(0.1) ; dot Wl ----
#pragma unroll
        for (int mi = 0; mi < 2; mi++)
#pragma unroll
            for (int rh = 0; rh < 2; rh++) {
                const int r = wm * 32 + mi * 16 + rh * 8 + lg;   // 0..63
                const int node = r >> 5, k = r & 31;
                const float wgt = swt[node * 32 + k];
                float p = 0.f;
#pragma unroll
                for (int ni = 0; ni < 4; ni++)
#pragma unroll
                    for (int cc = 0; cc < 2; cc++) {
                        const int d = wn * 32 + ni * 8 + 2 * lc + cc;
                        float h = acc[mi][ni][rh * 2 + cc] + sxs[node * 128 + d]
                                + fmaf(wgt, sWw[d], scb[d]);
                        h = fmaxf(h, 0.f) + 0.1f * fminf(h, 0.f);
                        p = fmaf(sWl[d], h, p);
                    }
                p += __shfl_xor_sync(0xffffffffu, p, 1);
                p += __shfl_xor_sync(0xffffffffu, p, 2);
                if (lc == 0) spart[r * 4 + wn] = p;
            }
        __syncthreads();   // sync2: spart ready; sA/sxs/swt reads complete

        // ---- softmax over K=32 per node (bl dropped: softmax-invariant) ----
        if (w < 2) {
            const int r = w * 32 + lane;    // node = w, k = lane
            float s = spart[r * 4] + spart[r * 4 + 1] + spart[r * 4 + 2] + spart[r * 4 + 3];
            float m = s;
#pragma unroll
            for (int o = 16; o; o >>= 1) m = fmaxf(m, __shfl_xor_sync(0xffffffffu, m, o));
            float e = expf(s - m);
            float su = e;
#pragma unroll
            for (int o = 16; o; o >>= 1) su += __shfl_xor_sync(0xffffffffu, su, o);
            sattn[r] = e / su;
        }
        __syncthreads();   // sync3: sattn ready; spart reads complete

        // ---- output: out[n,d] = sum_k attn[k] * x_nb[n,k,d]  (fp32, L1-hot) ----
        {
            const int node = tid >> 7, d = tid & 127;
            const long gn = (long)t * 2 + node;
            if (gn < N) {
                const float* src = x_nb + (gn * 32) * 128 + d;
                const float* at  = sattn + node * 32;
                float s0 = 0.f, s1 = 0.f;
#pragma unroll
                for (int k = 0; k < 32; k += 2) {
                    s0 = fmaf(at[k],     __ldg(src + k * 128),       s0);
                    s1 = fmaf(at[k + 1], __ldg(src + (k + 1) * 128), s1);
                }
                out[gn * 128 + d] = s0 + s1;
            }
        }
    }
}

// ---------------------------------------------------------------------------
extern "C" void kernel_launch(void* const* d_in, const int* in_sizes, int n_in,
                              void* d_out, int out_size)
{
    const float* x      = (const float*)d_in[0];
    const float* x_nb   = (const float*)d_in[1];
    const float* weight = (const float*)d_in[2];
    const float* Wx     = (const float*)d_in[3];
    const float* bx     = (const float*)d_in[4];
    const float* Wn     = (const float*)d_in[5];
    const float* bn     = (const float*)d_in[6];
    const float* Ww     = (const float*)d_in[7];
    const float* bw     = (const float*)d_in[8];
    const float* Wl     = (const float*)d_in[9];
    // d_in[10] = bl: softmax-invariant, unused.
    float* out = (float*)d_out;

    const int N = in_sizes[0] / 128;

    const size_t smem1 = (size_t)(128 * STX + 64 * STX + 128) * sizeof(float);
    cudaFuncSetAttribute(xs_kernel, cudaFuncAttributeMaxDynamicSharedMemorySize, (int)smem1);

    const size_t smem2 = SA_BYTES + SB_BYTES
                       + (256 + 64 + 256 + 64 + 128 + 128 + 128) * sizeof(float);
    cudaFuncSetAttribute(gnn_main_kernel, cudaFuncAttributeMaxDynamicSharedMemorySize, (int)smem2);

    int nSM = 148;
    cudaDeviceGetAttribute(&nSM, cudaDevAttrMultiProcessorCount, 0);

    const int blocks1 = (N + 63) / 64;
    xs_kernel<<<blocks1, 256, smem1>>>(x, Wx, bx, N);

    const int numTiles = (N + 1) / 2;
    int grid = 3 * nSM;
    if (grid > numTiles) grid = numTiles;
    gnn_main_kernel<<<grid, 256, smem2>>>(x_nb, weight, Wn, bn, Ww, bw, Wl, out, N, numTiles);
}